// round 13
// baseline (speedup 1.0000x reference)
#include <cuda_runtime.h>
#include <cuda_fp16.h>
#include <math.h>
#include <stdint.h>

typedef __half f16;

// ---------------------------------------------------------------------------
// Static scratch (zero-init at load; guard rows in g_XS never written).
// ---------------------------------------------------------------------------
__device__ f16 g_XeH[25165824];     // Xe fp16 [32768][768]
__device__ f16 g_XpH[10485760];     // Xp fp16 [32768][320]
__device__ f16 g_W1H[589824];       // W1 fp16 [768][768]
__device__ f16 g_W2H[245760];       // W2 fp16 [768][320]
__device__ f16 g_WcH[1769472];      // Wc fp16 [3 taps][768][768]
__device__ f16 g_XS [25264128];     // gated X fp16 [64][514][768], rows 0/513 zero guards
__device__ f16 g_PV [25165824];     // pv = tanh(C2+b2) fp16 [32768][768]
__device__ float g_pool[147456];    // pooled [64][768][3]

#define STAGES 3
#define STAGE_BYTES 32768              // 16KB A tile + 16KB B tile
#define SMEM_BYTES (STAGES * STAGE_BYTES)

// ------------------------------- PTX helpers -------------------------------
__device__ __forceinline__ uint32_t s2u(const void* p){
    uint32_t a;
    asm("{ .reg .u64 t; cvta.to.shared.u64 t, %1; cvt.u32.u64 %0, t; }"
        : "=r"(a) : "l"(p));
    return a;
}
#define SWZ(x) ((x) ^ (((x) >> 3) & 0x70))

__device__ __forceinline__ void cpa16(uint32_t d, const void* s){
    asm volatile("cp.async.cg.shared.global [%0], [%1], 16;" :: "r"(d), "l"(s));
}
__device__ __forceinline__ void ldsm4(uint32_t& r0, uint32_t& r1,
                                      uint32_t& r2, uint32_t& r3, uint32_t a){
    asm volatile("ldmatrix.sync.aligned.m8n8.x4.shared.b16 {%0,%1,%2,%3}, [%4];"
        : "=r"(r0), "=r"(r1), "=r"(r2), "=r"(r3) : "r"(a));
}
__device__ __forceinline__ void mma16816(float* d, const uint32_t* a,
                                         uint32_t b0, uint32_t b1){
    asm volatile("mma.sync.aligned.m16n8k16.row.col.f32.f16.f16.f32 "
        "{%0,%1,%2,%3},{%4,%5,%6,%7},{%8,%9},{%0,%1,%2,%3};"
        : "+f"(d[0]), "+f"(d[1]), "+f"(d[2]), "+f"(d[3])
        : "r"(a[0]), "r"(a[1]), "r"(a[2]), "r"(a[3]), "r"(b0), "r"(b1));
}

// ------------------------- GEMM building blocks ----------------------------
// Stage tile: A 128 rows x 64 f16 (128B SW128 rows), B same. 256 threads.
__device__ __forceinline__ void ld_stage(const char* Ap, const char* Bp,
                                         size_t kb, uint32_t sa){
    const int tid = threadIdx.x;
    uint32_t sb = sa + 16384;
    #pragma unroll
    for (int i = 0; i < 4; i++){
        int idx = tid + i * 256;        // 1024 = 128 rows x 8 16B-units
        int row = idx >> 3;
        int q   = (idx & 7) << 4;
        cpa16(sa + SWZ(row * 128 + q), Ap + (size_t)row * kb + q);
        cpa16(sb + SWZ(row * 128 + q), Bp + (size_t)row * kb + q);
    }
}

// pa[mi]/pb[g]: per-thread swizzled in-tile offsets (khalf folded in).
// Address for k-step ks = stage_base + (offset ^ (ks*32)); valid because the
// swizzle only XORs bits 7..9 into bits 4..6 and ks*32 occupies bits 5..6.
__device__ __forceinline__ void compute_stage(uint32_t sa,
                                              const uint32_t* pa,
                                              const uint32_t* pb,
                                              float acc[4][4][4]){
    uint32_t sb = sa + 16384;
    #pragma unroll
    for (int ks = 0; ks < 4; ks++){                   // 4 x k16 per BK=64
        const uint32_t kx = ks << 5;
        uint32_t a[4][4];
        #pragma unroll
        for (int mi = 0; mi < 4; mi++)
            ldsm4(a[mi][0], a[mi][1], a[mi][2], a[mi][3], sa + (pa[mi] ^ kx));
        uint32_t b[2][4];
        #pragma unroll
        for (int g = 0; g < 2; g++)
            ldsm4(b[g][0], b[g][1], b[g][2], b[g][3], sb + (pb[g] ^ kx));
        #pragma unroll
        for (int mi = 0; mi < 4; mi++)
            #pragma unroll
            for (int nj = 0; nj < 4; nj++)
                mma16816(acc[mi][nj], a[mi],
                         b[nj >> 1][(nj & 1) * 2], b[nj >> 1][(nj & 1) * 2 + 1]);
    }
}

// Pipelined GEMM over NTAP A/B base pairs, NPT BK=64 chunks each.
template <int NPT, int NTAP>
__device__ __forceinline__ void gemm_pipe(
    const f16* A0, const f16* A1, const f16* A2,
    const f16* B0, const f16* B1, const f16* B2,
    size_t kE, char* sm, float acc[4][4][4])
{
    const size_t kb = kE * 2;
    const char* At[3] = {(const char*)A0, (const char*)A1, (const char*)A2};
    const char* Bt[3] = {(const char*)B0, (const char*)B1, (const char*)B2};
    constexpr int nc = NPT * NTAP;
    const int wid  = threadIdx.x >> 5, lane = threadIdx.x & 31;
    const int wm   = wid & 1, wn = wid >> 1;
    const uint32_t smb = s2u(sm);

    // precomputed swizzled in-tile fragment offsets
    uint32_t pa[4], pb[2];
    {
        const uint32_t akh = (lane >> 4) << 4;
        #pragma unroll
        for (int mi = 0; mi < 4; mi++){
            int row = wm * 64 + mi * 16 + (lane & 15);
            pa[mi] = SWZ(row * 128) ^ akh;
        }
        const uint32_t bkh = ((lane >> 3) & 1) << 4;
        #pragma unroll
        for (int g = 0; g < 2; g++){
            int nrow = wn * 32 + g * 16 + (lane & 7) + ((lane >> 4) << 3);
            pb[g] = SWZ(nrow * 128) ^ bkh;
        }
    }

    #pragma unroll
    for (int i = 0; i < 4; i++)
        #pragma unroll
        for (int j = 0; j < 4; j++)
            #pragma unroll
            for (int r = 0; r < 4; r++) acc[i][j][r] = 0.f;

    #pragma unroll
    for (int s = 0; s < STAGES - 1; s++){
        ld_stage(At[0] + (size_t)s * 128, Bt[0] + (size_t)s * 128, kb,
                 smb + s * STAGE_BYTES);
        asm volatile("cp.async.commit_group;");
    }
    int tap = 0, kc = STAGES - 1;           // next chunk to load (NPT >= 5)

    #pragma unroll 1
    for (int c = 0; c < nc; c++){
        asm volatile("cp.async.wait_group 1;");
        __syncthreads();
        int nx = c + STAGES - 1;
        if (nx < nc){
            ld_stage(At[tap] + (size_t)kc * 128, Bt[tap] + (size_t)kc * 128,
                     kb, smb + (nx % STAGES) * STAGE_BYTES);
            if (++kc == NPT){ kc = 0; tap++; }
        }
        asm volatile("cp.async.commit_group;");   // empty group when tail
        compute_stage(smb + (c % STAGES) * STAGE_BYTES, pa, pb, acc);
    }
    __syncthreads();
}

// ------------------------------- GEMM kernels ------------------------------
// pv = tanh(XpH @ W2H^T + b2) (K=320), fp16 store.
__global__ __launch_bounds__(256, 2) void gemm_p_kernel(const float* __restrict__ b2){
    extern __shared__ char sm[];
    const int n0 = blockIdx.x * 128, m0 = blockIdx.y * 128;
    float acc[4][4][4];
    gemm_pipe<5, 1>(g_XpH + (size_t)m0 * 320, 0, 0,
                    g_W2H + (size_t)n0 * 320, 0, 0, 320, sm, acc);
    const int wid = threadIdx.x >> 5, lane = threadIdx.x & 31;
    const int wm = wid & 1, wn = wid >> 1;
    #pragma unroll
    for (int mi = 0; mi < 4; mi++)
        #pragma unroll
        for (int nj = 0; nj < 4; nj++){
            int col = n0 + wn * 32 + nj * 8 + (lane & 3) * 2;
            float b2a = b2[col], b2b = b2[col + 1];
            #pragma unroll
            for (int h = 0; h < 2; h++){
                int m = m0 + wm * 64 + mi * 16 + (lane >> 2) + h * 8;
                float p0 = tanhf(acc[mi][nj][h * 2]     + b2a);
                float p1 = tanhf(acc[mi][nj][h * 2 + 1] + b2b);
                *(__half2*)(g_PV + (size_t)m * 768 + col) = __floats2half2_rn(p0, p1);
            }
        }
}

// C1 = XeH @ W1H^T (K=768); epilogue: gate + mix -> fp16 X in g_XS.
__global__ __launch_bounds__(256, 2) void gemm_e_kernel(
    const float* __restrict__ Xe, const float* __restrict__ b1)
{
    extern __shared__ char sm[];
    const int n0 = blockIdx.x * 128, m0 = blockIdx.y * 128;
    float acc[4][4][4];
    gemm_pipe<12, 1>(g_XeH + (size_t)m0 * 768, 0, 0,
                     g_W1H + (size_t)n0 * 768, 0, 0, 768, sm, acc);
    const int wid = threadIdx.x >> 5, lane = threadIdx.x & 31;
    const int wm = wid & 1, wn = wid >> 1;
    const int bb = m0 >> 9;
    #pragma unroll
    for (int mi = 0; mi < 4; mi++)
        #pragma unroll
        for (int nj = 0; nj < 4; nj++){
            int col = n0 + wn * 32 + nj * 8 + (lane & 3) * 2;
            float b1a = b1[col], b1b = b1[col + 1];
            #pragma unroll
            for (int h = 0; h < 2; h++){
                int m = m0 + wm * 64 + mi * 16 + (lane >> 2) + h * 8;
                float2 xe = *(const float2*)(Xe + (size_t)m * 768 + col);
                __half2 pv = *(const __half2*)(g_PV + (size_t)m * 768 + col);
                float2 pvf = __half22float2(pv);
                float g0 = 1.f / (1.f + __expf(-(acc[mi][nj][h * 2]     + b1a)));
                float g1 = 1.f / (1.f + __expf(-(acc[mi][nj][h * 2 + 1] + b1b)));
                float X0 = g0 * xe.x + (1.f - g0) * pvf.x;
                float X1 = g1 * xe.y + (1.f - g1) * pvf.y;
                __half2 H = __floats2half2_rn(X0, X1);
                int rowp = bb * 514 + 1 + (m & 511);
                *(__half2*)(g_XS + (size_t)rowp * 768 + col) = H;
            }
        }
}

// Conv: 3 accumulating passes (A row-shifted by tap) + fused piecewise max-pool.
__global__ __launch_bounds__(256, 2) void gemm_c_kernel(
    const int* __restrict__ Xmask, const float* __restrict__ bc)
{
    extern __shared__ char sm[];
    const int n0 = blockIdx.x * 128, m0 = blockIdx.y * 128;
    const int bb = m0 >> 9, r0 = m0 & 511;
    const f16* Ab = g_XS  + (size_t)(bb * 514 + r0) * 768;   // tap t -> +t rows
    const f16* Bb = g_WcH + (size_t)n0 * 768;
    float acc[4][4][4];
    gemm_pipe<12, 3>(Ab, Ab + 768, Ab + 2 * 768,
                     Bb, Bb + 589824, Bb + 2 * 589824, 768, sm, acc);

    const int wid = threadIdx.x >> 5, lane = threadIdx.x & 31;
    const int wm = wid & 1, wn = wid >> 1;
    int* red = (int*)sm;                  // [3][128] float-bit maxima
    for (int e = threadIdx.x; e < 384; e += 256) red[e] = 0;
    __syncthreads();

    #pragma unroll
    for (int mi = 0; mi < 4; mi++)
        #pragma unroll
        for (int nj = 0; nj < 4; nj++){
            int col = n0 + wn * 32 + nj * 8 + (lane & 3) * 2;
            float bca = bc[col], bcb = bc[col + 1];
            #pragma unroll
            for (int h = 0; h < 2; h++){
                int m  = m0 + wm * 64 + mi * 16 + (lane >> 2) + h * 8;
                int mk = Xmask[m];
                if (mk){
                    int base = (mk - 1) * 128 + (col - n0);
                    atomicMax(&red[base],     __float_as_int(acc[mi][nj][h * 2]     + bca));
                    atomicMax(&red[base + 1], __float_as_int(acc[mi][nj][h * 2 + 1] + bcb));
                }
            }
        }
    __syncthreads();
    for (int e = threadIdx.x; e < 384; e += 256){
        int k = e >> 7, c = e & 127;
        atomicMax((int*)&g_pool[((size_t)bb * 768 + n0 + c) * 3 + k], red[e]);
    }
}

// ------------------------------ small kernels ------------------------------
__global__ __launch_bounds__(256) void cvt_xp_kernel(const float* __restrict__ in){
    int i = blockIdx.x * 256 + threadIdx.x;
    if (i >= 2621440) return;
    float4 v = *(const float4*)(in + (size_t)i * 4);
    __half2 a = __floats2half2_rn(v.x, v.y);
    __half2 b = __floats2half2_rn(v.z, v.w);
    uint2 u; u.x = *(uint32_t*)&a; u.y = *(uint32_t*)&b;
    *(uint2*)(g_XpH + (size_t)i * 4) = u;
}
__global__ __launch_bounds__(256) void cvt_w2_kernel(const float* __restrict__ in){
    int i = blockIdx.x * 256 + threadIdx.x;
    if (i >= 61440) return;
    float4 v = *(const float4*)(in + (size_t)i * 4);
    __half2 a = __floats2half2_rn(v.x, v.y);
    __half2 b = __floats2half2_rn(v.z, v.w);
    uint2 u; u.x = *(uint32_t*)&a; u.y = *(uint32_t*)&b;
    *(uint2*)(g_W2H + (size_t)i * 4) = u;
}

// Xe + W1 + Wc conversion + pool init, one grid.
__global__ __launch_bounds__(256) void prep_main_kernel(
    const float* __restrict__ Xe, const float* __restrict__ W1,
    const float* __restrict__ Wc)
{
    int blk = blockIdx.x;
    int t   = threadIdx.x;
    if (blk < 24576){
        int i = blk * 256 + t;
        float4 v = *(const float4*)(Xe + (size_t)i * 4);
        __half2 a = __floats2half2_rn(v.x, v.y);
        __half2 b = __floats2half2_rn(v.z, v.w);
        uint2 u; u.x = *(uint32_t*)&a; u.y = *(uint32_t*)&b;
        *(uint2*)(g_XeH + (size_t)i * 4) = u;
    } else if (blk < 25152){
        int i = (blk - 24576) * 256 + t;
        float4 v = *(const float4*)(W1 + (size_t)i * 4);
        __half2 a = __floats2half2_rn(v.x, v.y);
        __half2 b = __floats2half2_rn(v.z, v.w);
        uint2 u; u.x = *(uint32_t*)&a; u.y = *(uint32_t*)&b;
        *(uint2*)(g_W1H + (size_t)i * 4) = u;
    } else if (blk < 27456){
        int idx = (blk - 25152) * 256 + t;
        const float* src = Wc + (size_t)idx * 3;
        #pragma unroll
        for (int tp = 0; tp < 3; tp++)
            g_WcH[(size_t)tp * 589824 + idx] = __float2half_rn(src[tp]);
    } else {
        int i = (blk - 27456) * 256 + t;
        g_pool[i] = 0.f;
    }
}

__global__ void final_kernel(float* __restrict__ out){
    int i = blockIdx.x * 256 + threadIdx.x;
    if (i < 147456) out[i] = tanhf(g_pool[i]);
}

// ---------------------------------------------------------------------------
extern "C" void kernel_launch(void* const* d_in, const int* in_sizes, int n_in,
                              void* d_out, int out_size)
{
    const float* Xp = (const float*)d_in[0];
    const float* Xe = (const float*)d_in[1];
    const int*   Xm = (const int*)  d_in[2];
    const float* W1 = (const float*)d_in[3];
    const float* b1 = (const float*)d_in[4];
    const float* W2 = (const float*)d_in[5];
    const float* b2 = (const float*)d_in[6];
    const float* Wc = (const float*)d_in[7];
    const float* bc = (const float*)d_in[8];
    float* out = (float*)d_out;

    cudaFuncSetAttribute(gemm_p_kernel, cudaFuncAttributeMaxDynamicSharedMemorySize, SMEM_BYTES);
    cudaFuncSetAttribute(gemm_e_kernel, cudaFuncAttributeMaxDynamicSharedMemorySize, SMEM_BYTES);
    cudaFuncSetAttribute(gemm_c_kernel, cudaFuncAttributeMaxDynamicSharedMemorySize, SMEM_BYTES);

    // launch order chosen so ncu (-s 5 -c 1) captures gemm_c_kernel (launch #6)
    cvt_xp_kernel<<<10240, 256>>>(Xp);                 // 1
    cvt_w2_kernel<<<240, 256>>>(W2);                   // 2
    prep_main_kernel<<<28032, 256>>>(Xe, W1, Wc);      // 3

    dim3 gg(6, 256);   // 6 N-tiles x 256 M-tiles
    gemm_p_kernel<<<gg, 256, SMEM_BYTES>>>(b2);        // 4
    gemm_e_kernel<<<gg, 256, SMEM_BYTES>>>(Xe, b1);    // 5
    gemm_c_kernel<<<gg, 256, SMEM_BYTES>>>(Xm, bc);    // 6  <- ncu capture
    final_kernel<<<576, 256>>>(out);                   // 7
}